// round 8
// baseline (speedup 1.0000x reference)
#include <cuda_runtime.h>
#include <cstdint>

#define NAG   4096
#define TOPK  12
#define NSEL  13                 // extract 13, fix up ordering with real sqrt
#define NITEMS (NAG * TOPK)      // 49152
#define T1    256                // threads, streaming kernel
#define EPT   16                 // elements per thread = 4096/256
#define CCAP  256                // per-row candidate capacity

// fused MLP tiling
#define TILE_I 64                // items per block
#define HSTR   64                // row stride (floats) -- broadcast/consecutive
#define SMEM_FLOATS ((64 + 128) * HSTR)
#define SMEM_BYTES  (SMEM_FLOATS * 4)   // 49,152 B dynamic -> 4 blocks/SM

#define U64MAX 0xFFFFFFFFFFFFFFFFULL

__device__ int   g_topk_idx[NITEMS];
__device__ float g_W2t[64 * 128];        // [k][m]
__device__ float g_W3t[128 * 64];        // [k][o]
__device__ unsigned long long g_cand[NAG * CCAP];   // 8 MB candidate buffer
__device__ int   g_cnt[NAG];

static __device__ __forceinline__ unsigned long long
u64min(unsigned long long a, unsigned long long b) { return (b < a) ? b : a; }

// ---------------------------------------------------------------------------
// Kernel 1a: pure streaming candidate filter (proven round 7, unchanged).
// ---------------------------------------------------------------------------
__global__ void __launch_bounds__(T1) topk_filter_kernel(const float* __restrict__ x) {
    const int i    = blockIdx.x;
    const int tid  = threadIdx.x;
    const int w    = tid >> 5;
    const int lane = tid & 31;
    const float* row = x + (size_t)i * (NAG * 4);

    unsigned sb[EPT];
#pragma unroll
    for (int t = 0; t < EPT; ++t) {
        const int j = tid + t * T1;
        const float2 v = *reinterpret_cast<const float2*>(row + (size_t)j * 4);
        const float s = __fadd_rn(__fadd_rn(__fmul_rn(v.x, v.x), 1e-6f),
                                  __fadd_rn(__fmul_rn(v.y, v.y), 1e-6f));
        sb[t] = __float_as_uint(s);
    }

    unsigned mymin = sb[0];
#pragma unroll
    for (int t = 1; t < EPT; ++t) mymin = (sb[t] < mymin) ? sb[t] : mymin;

    __shared__ unsigned tmin[T1];
    __shared__ unsigned sthresh;
    __shared__ int      scnt;

    tmin[tid] = mymin;
    if (tid == 0) scnt = 0;
    __syncthreads();

    // threshold: max of 13 group minima (12 groups of 20 + 1 group of 16)
    if (w == 0 && lane < 13) {
        const int start = lane * 20;
        const int len   = (lane == 12) ? 16 : 20;
        unsigned g = tmin[start];
        for (int q = 1; q < len; ++q) {
            const unsigned v = tmin[start + q];
            g = (v < g) ? v : g;
        }
        const unsigned mx = __reduce_max_sync(0x1FFFu, g);
        if (lane == 0) sthresh = mx;
    }
    __syncthreads();

    const unsigned thr = sthresh;
    unsigned long long* cand = g_cand + (size_t)i * CCAP;
#pragma unroll
    for (int t = 0; t < EPT; ++t) {
        if (sb[t] <= thr) {
            const int pos = atomicAdd(&scnt, 1);
            if (pos < CCAP)
                cand[pos] = ((unsigned long long)sb[t] << 32)
                          | (unsigned)(tid + t * T1);
        }
    }
    __syncthreads();
    if (tid == 0) g_cnt[i] = scnt;
}

// ---------------------------------------------------------------------------
// Kernel 1b: one warp per row; 13 ascending extract-min passes + sqrt fixup
// (proven round 7, unchanged).
// ---------------------------------------------------------------------------
__global__ void __launch_bounds__(256) topk_extract_kernel(const float* __restrict__ x) {
    const int tid  = threadIdx.x;
    const int lane = tid & 31;
    const int i    = blockIdx.x * 8 + (tid >> 5);
    const int n    = g_cnt[i];

    unsigned long long fk[NSEL];
    unsigned long long prev = 0;      // keys >= 2^32 > 0

    if (n <= CCAP) {
        const unsigned long long* cand = g_cand + (size_t)i * CCAP;
        unsigned long long ck[8];     // CCAP/32 = 8
#pragma unroll
        for (int t = 0; t < 8; ++t) {
            const int idx = lane + t * 32;
            ck[t] = (idx < n) ? cand[idx] : U64MAX;
        }
#pragma unroll 1
        for (int pass = 0; pass < NSEL; ++pass) {
            unsigned long long lmin = U64MAX;
#pragma unroll
            for (int t = 0; t < 8; ++t)
                if (ck[t] > prev) lmin = u64min(lmin, ck[t]);
            unsigned long long v = lmin;
#pragma unroll
            for (int off = 16; off > 0; off >>= 1) {
                const unsigned long long o = __shfl_xor_sync(0xffffffffu, v, off);
                v = u64min(v, o);
            }
            fk[pass] = v;
            prev = v;
        }
    } else {
        // overflow fallback: rescan the row directly (deterministic, rare)
        const float* row = x + (size_t)i * (NAG * 4);
#pragma unroll 1
        for (int pass = 0; pass < NSEL; ++pass) {
            unsigned long long lmin = U64MAX;
            for (int t = 0; t < NAG / 32; ++t) {
                const int j = lane + t * 32;
                const float2 v2 = *reinterpret_cast<const float2*>(row + (size_t)j * 4);
                const float s = __fadd_rn(__fadd_rn(__fmul_rn(v2.x, v2.x), 1e-6f),
                                          __fadd_rn(__fmul_rn(v2.y, v2.y), 1e-6f));
                const unsigned long long k =
                    ((unsigned long long)__float_as_uint(s) << 32) | (unsigned)j;
                if (k > prev) lmin = u64min(lmin, k);
            }
            unsigned long long v = lmin;
#pragma unroll
            for (int off = 16; off > 0; off >>= 1) {
                const unsigned long long o = __shfl_xor_sync(0xffffffffu, v, off);
                v = u64min(v, o);
            }
            fk[pass] = v;
            prev = v;
        }
    }

    // fixup on lane 0: re-key by (sqrt_bits, j), insertion sort, keep 12
    if (lane == 0) {
#pragma unroll
        for (int t = 0; t < NSEL; ++t) {
            const unsigned long long k = fk[t];
            const float s  = __uint_as_float((unsigned)(k >> 32));
            const float dn = __fsqrt_rn(s);
            fk[t] = ((unsigned long long)__float_as_uint(dn) << 32)
                  | (k & 0xFFFFFFFFULL);
        }
#pragma unroll
        for (int a = 1; a < NSEL; ++a) {
            const unsigned long long key = fk[a];
            int b = a - 1;
#pragma unroll
            for (int q = 0; q < NSEL - 1; ++q) {
                if (b >= 0 && fk[b] > key) { fk[b + 1] = fk[b]; b--; }
            }
            fk[b + 1] = key;
        }
#pragma unroll
        for (int t = 0; t < TOPK; ++t)
            g_topk_idx[i * TOPK + t] = (int)(unsigned)(fk[t] & 0xFFFFFFFFULL);
    }
}

// ---------------------------------------------------------------------------
// Kernel T: transpose (now parallel: 32 blocks, grid-stride)
// ---------------------------------------------------------------------------
__global__ void __launch_bounds__(256) transpose_kernel(
    const float* __restrict__ W2, const float* __restrict__ W3)
{
    const int g = blockIdx.x * 256 + threadIdx.x;
    const int stride = gridDim.x * 256;
    for (int s = g; s < 128 * 64; s += stride) {
        const int m = s >> 6, k = s & 63;
        g_W2t[k * 128 + m] = W2[s];
    }
    for (int s = g; s < 64 * 128; s += stride) {
        const int o = s >> 7, m = s & 127;
        g_W3t[m * 64 + o] = W3[s];
    }
}

// ---------------------------------------------------------------------------
// Fused MLP kernel: per block = 64 items; now 4 blocks/SM (48 KB smem,
// <=64 regs via launch_bounds(256,4) + register diet in the GEMM stages).
// ---------------------------------------------------------------------------
__global__ void __launch_bounds__(256, 4) fused_mlp_kernel(
    const float* __restrict__ x,  const float* __restrict__ rp,
    const float* __restrict__ W1, const float* __restrict__ b1,
    const float* __restrict__ b2, const float* __restrict__ b3,
    const float* __restrict__ W4, const float* __restrict__ b4,
    float* __restrict__ out)
{
    extern __shared__ float smem[];
    float* H1s = smem;                   // [64][HSTR]
    float* H2s = smem + 64 * HSTR;       // [128][HSTR]
    float* red = smem;                   // reuse H1s area after stage B

    __shared__ float W1s[64 * 6];
    __shared__ float b1s[64];
    __shared__ float masks[TILE_I];

    const int tid = threadIdx.x;
    for (int s = tid; s < 384; s += 256) W1s[s] = W1[s];
    if (tid < 64) b1s[tid] = b1[tid];
    __syncthreads();

    // ---------------- stage A: features + layer1 (6 -> 64) ----------------
    {
        const int iloc = tid & 63;
        const int q    = tid >> 6;           // 4 threads per item
        const int item = blockIdx.x * TILE_I + iloc;
        const int i = item / TOPK;
        const int j = g_topk_idx[item];

        const float4 v = *reinterpret_cast<const float4*>(
            x + ((size_t)i * NAG + (size_t)j) * 4);
        const float s2 = __fadd_rn(__fadd_rn(__fmul_rn(v.x, v.x), 1e-4f),
                                   __fadd_rn(__fmul_rn(v.y, v.y), 1e-4f));
        const float dn = __fsqrt_rn(s2);
        const float r  = rp[0];
        const float mk = (dn <= 1.0f) ? 1.0f : 0.0f;
        const float f0 = v.x, f1 = v.y, f2 = v.z, f3 = v.w;
        const float f4 = (i == j) ? 1.0f : 0.0f;
        const float f5 = dn - r;

        const int o0 = q * 16;
#pragma unroll
        for (int oo = 0; oo < 16; ++oo) {
            const int o = o0 + oo;
            const float* wp = W1s + o * 6;
            float a = b1s[o];
            a = fmaf(wp[0], f0, a); a = fmaf(wp[1], f1, a); a = fmaf(wp[2], f2, a);
            a = fmaf(wp[3], f3, a); a = fmaf(wp[4], f4, a); a = fmaf(wp[5], f5, a);
            H1s[o * HSTR + iloc] = fmaxf(a, 0.0f);
        }

        if (q == 0) {
            masks[iloc] = mk;
            out[NITEMS + item] = mk;
            out[2 * NITEMS + 2 * item + 0] = (float)i;
            out[2 * NITEMS + 2 * item + 1] = (float)j;
        }
    }
    __syncthreads();

    // ------------- stage B: layer2 GEMM (K=64), 4m x 8i tiles --------------
    {
        const int m0 = (tid >> 3) * 4;       // 0..124
        const int i0 = (tid & 7) * 8;        // 0..56

        float acc[4][8];
#pragma unroll
        for (int mm = 0; mm < 4; ++mm) {
            const float b = b2[m0 + mm];
#pragma unroll
            for (int ii = 0; ii < 8; ++ii) acc[mm][ii] = b;
        }

#pragma unroll 2
        for (int k = 0; k < 64; ++k) {
            const float4 a  = *reinterpret_cast<const float4*>(g_W2t + k * 128 + m0);
            const float4 x0 = *reinterpret_cast<const float4*>(H1s + k * HSTR + i0);
            const float4 x1 = *reinterpret_cast<const float4*>(H1s + k * HSTR + i0 + 4);
            acc[0][0] = fmaf(a.x, x0.x, acc[0][0]); acc[0][1] = fmaf(a.x, x0.y, acc[0][1]);
            acc[0][2] = fmaf(a.x, x0.z, acc[0][2]); acc[0][3] = fmaf(a.x, x0.w, acc[0][3]);
            acc[0][4] = fmaf(a.x, x1.x, acc[0][4]); acc[0][5] = fmaf(a.x, x1.y, acc[0][5]);
            acc[0][6] = fmaf(a.x, x1.z, acc[0][6]); acc[0][7] = fmaf(a.x, x1.w, acc[0][7]);
            acc[1][0] = fmaf(a.y, x0.x, acc[1][0]); acc[1][1] = fmaf(a.y, x0.y, acc[1][1]);
            acc[1][2] = fmaf(a.y, x0.z, acc[1][2]); acc[1][3] = fmaf(a.y, x0.w, acc[1][3]);
            acc[1][4] = fmaf(a.y, x1.x, acc[1][4]); acc[1][5] = fmaf(a.y, x1.y, acc[1][5]);
            acc[1][6] = fmaf(a.y, x1.z, acc[1][6]); acc[1][7] = fmaf(a.y, x1.w, acc[1][7]);
            acc[2][0] = fmaf(a.z, x0.x, acc[2][0]); acc[2][1] = fmaf(a.z, x0.y, acc[2][1]);
            acc[2][2] = fmaf(a.z, x0.z, acc[2][2]); acc[2][3] = fmaf(a.z, x0.w, acc[2][3]);
            acc[2][4] = fmaf(a.z, x1.x, acc[2][4]); acc[2][5] = fmaf(a.z, x1.y, acc[2][5]);
            acc[2][6] = fmaf(a.z, x1.z, acc[2][6]); acc[2][7] = fmaf(a.z, x1.w, acc[2][7]);
            acc[3][0] = fmaf(a.w, x0.x, acc[3][0]); acc[3][1] = fmaf(a.w, x0.y, acc[3][1]);
            acc[3][2] = fmaf(a.w, x0.z, acc[3][2]); acc[3][3] = fmaf(a.w, x0.w, acc[3][3]);
            acc[3][4] = fmaf(a.w, x1.x, acc[3][4]); acc[3][5] = fmaf(a.w, x1.y, acc[3][5]);
            acc[3][6] = fmaf(a.w, x1.z, acc[3][6]); acc[3][7] = fmaf(a.w, x1.w, acc[3][7]);
        }

#pragma unroll
        for (int mm = 0; mm < 4; ++mm) {
            float* dst = H2s + (m0 + mm) * HSTR + i0;
            float4 s0, s1;
            s0.x = fmaxf(acc[mm][0], 0.f); s0.y = fmaxf(acc[mm][1], 0.f);
            s0.z = fmaxf(acc[mm][2], 0.f); s0.w = fmaxf(acc[mm][3], 0.f);
            s1.x = fmaxf(acc[mm][4], 0.f); s1.y = fmaxf(acc[mm][5], 0.f);
            s1.z = fmaxf(acc[mm][6], 0.f); s1.w = fmaxf(acc[mm][7], 0.f);
            *reinterpret_cast<float4*>(dst)     = s0;
            *reinterpret_cast<float4*>(dst + 4) = s1;
        }
    }
    __syncthreads();

    // ------- stage C: layer3 GEMM (K=128), 4o x 4i tiles + layer4 ----------
    {
        const int o0 = (tid >> 4) * 4;       // 0..60
        const int i0 = (tid & 15) * 4;       // 0..60

        float acc[4][4];
#pragma unroll
        for (int mm = 0; mm < 4; ++mm) {
            const float b = b3[o0 + mm];
#pragma unroll
            for (int ii = 0; ii < 4; ++ii) acc[mm][ii] = b;
        }

#pragma unroll 2
        for (int k = 0; k < 128; ++k) {
            const float4 a  = *reinterpret_cast<const float4*>(g_W3t + k * 64 + o0);
            const float4 x0 = *reinterpret_cast<const float4*>(H2s + k * HSTR + i0);
            acc[0][0] = fmaf(a.x, x0.x, acc[0][0]); acc[0][1] = fmaf(a.x, x0.y, acc[0][1]);
            acc[0][2] = fmaf(a.x, x0.z, acc[0][2]); acc[0][3] = fmaf(a.x, x0.w, acc[0][3]);
            acc[1][0] = fmaf(a.y, x0.x, acc[1][0]); acc[1][1] = fmaf(a.y, x0.y, acc[1][1]);
            acc[1][2] = fmaf(a.y, x0.z, acc[1][2]); acc[1][3] = fmaf(a.y, x0.w, acc[1][3]);
            acc[2][0] = fmaf(a.z, x0.x, acc[2][0]); acc[2][1] = fmaf(a.z, x0.y, acc[2][1]);
            acc[2][2] = fmaf(a.z, x0.z, acc[2][2]); acc[2][3] = fmaf(a.z, x0.w, acc[2][3]);
            acc[3][0] = fmaf(a.w, x0.x, acc[3][0]); acc[3][1] = fmaf(a.w, x0.y, acc[3][1]);
            acc[3][2] = fmaf(a.w, x0.z, acc[3][2]); acc[3][3] = fmaf(a.w, x0.w, acc[3][3]);
        }

        // partial layer4 dot over this thread's 4 o's (into reused H1s area)
        const float4 w4 = *reinterpret_cast<const float4*>(W4 + o0);
        const int to = tid >> 4;
#pragma unroll
        for (int ii = 0; ii < 4; ++ii) {
            float p;
            p = __fmul_rn(w4.x, fmaxf(acc[0][ii], 0.f));
            p = fmaf(w4.y, fmaxf(acc[1][ii], 0.f), p);
            p = fmaf(w4.z, fmaxf(acc[2][ii], 0.f), p);
            p = fmaf(w4.w, fmaxf(acc[3][ii], 0.f), p);
            red[to * HSTR + i0 + ii] = p;
        }
    }
    __syncthreads();

    // final: one thread per item sums 16 partials
    if (tid < TILE_I) {
        const int item = blockIdx.x * TILE_I + tid;
        float s = red[tid];
#pragma unroll
        for (int g = 1; g < 16; ++g) s += red[g * HSTR + tid];
        out[item] = (s + b4[0]) * masks[tid];
    }
}

extern "C" void kernel_launch(void* const* d_in, const int* in_sizes, int n_in,
                              void* d_out, int out_size) {
    const float* x  = (const float*)d_in[0];
    const float* r  = (const float*)d_in[1];
    const float* W1 = (const float*)d_in[2];
    const float* b1 = (const float*)d_in[3];
    const float* W2 = (const float*)d_in[4];
    const float* b2 = (const float*)d_in[5];
    const float* W3 = (const float*)d_in[6];
    const float* b3 = (const float*)d_in[7];
    const float* W4 = (const float*)d_in[8];
    const float* b4 = (const float*)d_in[9];
    float* out = (float*)d_out;

    cudaFuncSetAttribute(fused_mlp_kernel,
                         cudaFuncAttributeMaxDynamicSharedMemorySize, SMEM_BYTES);

    topk_filter_kernel<<<NAG, T1>>>(x);
    topk_extract_kernel<<<NAG / 8, 256>>>(x);
    transpose_kernel<<<32, 256>>>(W2, W3);
    fused_mlp_kernel<<<NITEMS / TILE_I, 256, SMEM_BYTES>>>(
        x, r, W1, b1, b2, b3, W4, b4, out);
}

// round 9
// speedup vs baseline: 1.1967x; 1.1967x over previous
#include <cuda_runtime.h>
#include <cstdint>

#define NAG   4096
#define TOPK  12
#define NSEL  13                 // extract 13, fix up ordering with real sqrt
#define NITEMS (NAG * TOPK)      // 49152
#define T1    256                // threads, streaming kernel
#define EPT   16                 // elements per thread = 4096/256
#define CCAP  256                // per-row candidate capacity

// fused MLP tiling (round-7 proven geometry)
#define TILE_I 64                // items per block
#define HSTR   68                // padded row stride (floats), 272B = 17*16 ok
#define SMEM_FLOATS ((64 + 128) * HSTR)
#define SMEM_BYTES  (SMEM_FLOATS * 4)   // 52,224 B dynamic -> 3 blocks/SM

#define U64MAX 0xFFFFFFFFFFFFFFFFULL

__device__ int   g_topk_idx[NITEMS];
__device__ float g_W2t[64 * 128];        // [k][m]
__device__ float g_W3t[128 * 64];        // [k][o]
__device__ unsigned long long g_cand[NAG * CCAP];   // 8 MB candidate buffer
__device__ int   g_cnt[NAG];

static __device__ __forceinline__ unsigned long long
u64min(unsigned long long a, unsigned long long b) { return (b < a) ? b : a; }

// ---- packed f32x2 helpers (bitwise identical to two scalar fmaf's) --------
static __device__ __forceinline__ unsigned long long pk2(float lo, float hi) {
    unsigned long long r;
    asm("mov.b64 %0, {%1, %2};" : "=l"(r) : "f"(lo), "f"(hi));
    return r;
}
static __device__ __forceinline__ unsigned long long
fma2(unsigned long long a, unsigned long long b, unsigned long long c) {
    unsigned long long d;
    asm("fma.rn.f32x2 %0, %1, %2, %3;" : "=l"(d) : "l"(a), "l"(b), "l"(c));
    return d;
}
static __device__ __forceinline__ float2 up2(unsigned long long v) {
    float2 f;
    asm("mov.b64 {%0, %1}, %2;" : "=f"(f.x), "=f"(f.y) : "l"(v));
    return f;
}

// ---------------------------------------------------------------------------
// Kernel 1a: pure streaming candidate filter (proven round 7, unchanged).
// ---------------------------------------------------------------------------
__global__ void __launch_bounds__(T1) topk_filter_kernel(const float* __restrict__ x) {
    const int i    = blockIdx.x;
    const int tid  = threadIdx.x;
    const int w    = tid >> 5;
    const int lane = tid & 31;
    const float* row = x + (size_t)i * (NAG * 4);

    unsigned sb[EPT];
#pragma unroll
    for (int t = 0; t < EPT; ++t) {
        const int j = tid + t * T1;
        const float2 v = *reinterpret_cast<const float2*>(row + (size_t)j * 4);
        const float s = __fadd_rn(__fadd_rn(__fmul_rn(v.x, v.x), 1e-6f),
                                  __fadd_rn(__fmul_rn(v.y, v.y), 1e-6f));
        sb[t] = __float_as_uint(s);
    }

    unsigned mymin = sb[0];
#pragma unroll
    for (int t = 1; t < EPT; ++t) mymin = (sb[t] < mymin) ? sb[t] : mymin;

    __shared__ unsigned tmin[T1];
    __shared__ unsigned sthresh;
    __shared__ int      scnt;

    tmin[tid] = mymin;
    if (tid == 0) scnt = 0;
    __syncthreads();

    // threshold: max of 13 group minima (12 groups of 20 + 1 group of 16)
    if (w == 0 && lane < 13) {
        const int start = lane * 20;
        const int len   = (lane == 12) ? 16 : 20;
        unsigned g = tmin[start];
        for (int q = 1; q < len; ++q) {
            const unsigned v = tmin[start + q];
            g = (v < g) ? v : g;
        }
        const unsigned mx = __reduce_max_sync(0x1FFFu, g);
        if (lane == 0) sthresh = mx;
    }
    __syncthreads();

    const unsigned thr = sthresh;
    unsigned long long* cand = g_cand + (size_t)i * CCAP;
#pragma unroll
    for (int t = 0; t < EPT; ++t) {
        if (sb[t] <= thr) {
            const int pos = atomicAdd(&scnt, 1);
            if (pos < CCAP)
                cand[pos] = ((unsigned long long)sb[t] << 32)
                          | (unsigned)(tid + t * T1);
        }
    }
    __syncthreads();
    if (tid == 0) g_cnt[i] = scnt;
}

// ---------------------------------------------------------------------------
// Kernel 1b: one warp per row; 13 ascending extract-min passes + sqrt fixup
// (proven round 7, unchanged).
// ---------------------------------------------------------------------------
__global__ void __launch_bounds__(256) topk_extract_kernel(const float* __restrict__ x) {
    const int tid  = threadIdx.x;
    const int lane = tid & 31;
    const int i    = blockIdx.x * 8 + (tid >> 5);
    const int n    = g_cnt[i];

    unsigned long long fk[NSEL];
    unsigned long long prev = 0;      // keys >= 2^32 > 0

    if (n <= CCAP) {
        const unsigned long long* cand = g_cand + (size_t)i * CCAP;
        unsigned long long ck[8];     // CCAP/32 = 8
#pragma unroll
        for (int t = 0; t < 8; ++t) {
            const int idx = lane + t * 32;
            ck[t] = (idx < n) ? cand[idx] : U64MAX;
        }
#pragma unroll 1
        for (int pass = 0; pass < NSEL; ++pass) {
            unsigned long long lmin = U64MAX;
#pragma unroll
            for (int t = 0; t < 8; ++t)
                if (ck[t] > prev) lmin = u64min(lmin, ck[t]);
            unsigned long long v = lmin;
#pragma unroll
            for (int off = 16; off > 0; off >>= 1) {
                const unsigned long long o = __shfl_xor_sync(0xffffffffu, v, off);
                v = u64min(v, o);
            }
            fk[pass] = v;
            prev = v;
        }
    } else {
        // overflow fallback: rescan the row directly (deterministic, rare)
        const float* row = x + (size_t)i * (NAG * 4);
#pragma unroll 1
        for (int pass = 0; pass < NSEL; ++pass) {
            unsigned long long lmin = U64MAX;
            for (int t = 0; t < NAG / 32; ++t) {
                const int j = lane + t * 32;
                const float2 v2 = *reinterpret_cast<const float2*>(row + (size_t)j * 4);
                const float s = __fadd_rn(__fadd_rn(__fmul_rn(v2.x, v2.x), 1e-6f),
                                          __fadd_rn(__fmul_rn(v2.y, v2.y), 1e-6f));
                const unsigned long long k =
                    ((unsigned long long)__float_as_uint(s) << 32) | (unsigned)j;
                if (k > prev) lmin = u64min(lmin, k);
            }
            unsigned long long v = lmin;
#pragma unroll
            for (int off = 16; off > 0; off >>= 1) {
                const unsigned long long o = __shfl_xor_sync(0xffffffffu, v, off);
                v = u64min(v, o);
            }
            fk[pass] = v;
            prev = v;
        }
    }

    // fixup on lane 0: re-key by (sqrt_bits, j), insertion sort, keep 12
    if (lane == 0) {
#pragma unroll
        for (int t = 0; t < NSEL; ++t) {
            const unsigned long long k = fk[t];
            const float s  = __uint_as_float((unsigned)(k >> 32));
            const float dn = __fsqrt_rn(s);
            fk[t] = ((unsigned long long)__float_as_uint(dn) << 32)
                  | (k & 0xFFFFFFFFULL);
        }
#pragma unroll
        for (int a = 1; a < NSEL; ++a) {
            const unsigned long long key = fk[a];
            int b = a - 1;
#pragma unroll
            for (int q = 0; q < NSEL - 1; ++q) {
                if (b >= 0 && fk[b] > key) { fk[b + 1] = fk[b]; b--; }
            }
            fk[b + 1] = key;
        }
#pragma unroll
        for (int t = 0; t < TOPK; ++t)
            g_topk_idx[i * TOPK + t] = (int)(unsigned)(fk[t] & 0xFFFFFFFFULL);
    }
}

// ---------------------------------------------------------------------------
// Kernel T: transpose (parallel grid-stride)
// ---------------------------------------------------------------------------
__global__ void __launch_bounds__(256) transpose_kernel(
    const float* __restrict__ W2, const float* __restrict__ W3)
{
    const int g = blockIdx.x * 256 + threadIdx.x;
    const int stride = gridDim.x * 256;
    for (int s = g; s < 128 * 64; s += stride) {
        const int m = s >> 6, k = s & 63;
        g_W2t[k * 128 + m] = W2[s];
    }
    for (int s = g; s < 64 * 128; s += stride) {
        const int o = s >> 7, m = s & 127;
        g_W3t[m * 64 + o] = W3[s];
    }
}

// ---------------------------------------------------------------------------
// Fused MLP kernel: round-7 geometry (64 items/block, 3 blocks/SM), GEMM
// inner loops converted to packed fma.rn.f32x2 along the item dimension
// (operands loaded directly as ulonglong2 from smem; weights dup'd once/k).
// ---------------------------------------------------------------------------
__global__ void __launch_bounds__(256, 3) fused_mlp_kernel(
    const float* __restrict__ x,  const float* __restrict__ rp,
    const float* __restrict__ W1, const float* __restrict__ b1,
    const float* __restrict__ b2, const float* __restrict__ b3,
    const float* __restrict__ W4, const float* __restrict__ b4,
    float* __restrict__ out)
{
    extern __shared__ float smem[];
    float* H1s = smem;                   // [64][HSTR]
    float* H2s = smem + 64 * HSTR;       // [128][HSTR]
    float* red = smem;                   // reuse H1s area after stage B

    __shared__ float W1s[64 * 6];
    __shared__ float b1s[64];
    __shared__ float masks[TILE_I];

    const int tid = threadIdx.x;
    for (int s = tid; s < 384; s += 256) W1s[s] = W1[s];
    if (tid < 64) b1s[tid] = b1[tid];
    __syncthreads();

    // ---------------- stage A: features + layer1 (6 -> 64) ----------------
    {
        const int iloc = tid & 63;
        const int q    = tid >> 6;           // 4 threads per item
        const int item = blockIdx.x * TILE_I + iloc;
        const int i = item / TOPK;
        const int j = g_topk_idx[item];

        const float4 v = *reinterpret_cast<const float4*>(
            x + ((size_t)i * NAG + (size_t)j) * 4);
        const float s2 = __fadd_rn(__fadd_rn(__fmul_rn(v.x, v.x), 1e-4f),
                                   __fadd_rn(__fmul_rn(v.y, v.y), 1e-4f));
        const float dn = __fsqrt_rn(s2);
        const float r  = rp[0];
        const float mk = (dn <= 1.0f) ? 1.0f : 0.0f;
        const float f0 = v.x, f1 = v.y, f2 = v.z, f3 = v.w;
        const float f4 = (i == j) ? 1.0f : 0.0f;
        const float f5 = dn - r;

        const int o0 = q * 16;
#pragma unroll
        for (int oo = 0; oo < 16; ++oo) {
            const int o = o0 + oo;
            const float* wp = W1s + o * 6;
            float a = b1s[o];
            a = fmaf(wp[0], f0, a); a = fmaf(wp[1], f1, a); a = fmaf(wp[2], f2, a);
            a = fmaf(wp[3], f3, a); a = fmaf(wp[4], f4, a); a = fmaf(wp[5], f5, a);
            H1s[o * HSTR + iloc] = fmaxf(a, 0.0f);
        }

        if (q == 0) {
            masks[iloc] = mk;
            out[NITEMS + item] = mk;
            out[2 * NITEMS + 2 * item + 0] = (float)i;
            out[2 * NITEMS + 2 * item + 1] = (float)j;
        }
    }
    __syncthreads();

    // ------------- stage B: layer2 GEMM (K=64), 4m x 8i tiles, f32x2 -------
    {
        const int m0 = (tid >> 3) * 4;       // 0..124
        const int i0 = (tid & 7) * 8;        // 0..56

        unsigned long long pacc[4][4];       // [mm][item-pair]
#pragma unroll
        for (int mm = 0; mm < 4; ++mm) {
            const float b = b2[m0 + mm];
            const unsigned long long pb = pk2(b, b);
#pragma unroll
            for (int p = 0; p < 4; ++p) pacc[mm][p] = pb;
        }

#pragma unroll 4
        for (int k = 0; k < 64; ++k) {
            const float4 a = *reinterpret_cast<const float4*>(g_W2t + k * 128 + m0);
            const ulonglong2 xa =
                *reinterpret_cast<const ulonglong2*>(H1s + k * HSTR + i0);
            const ulonglong2 xb =
                *reinterpret_cast<const ulonglong2*>(H1s + k * HSTR + i0 + 4);
            const unsigned long long ax = pk2(a.x, a.x);
            const unsigned long long ay = pk2(a.y, a.y);
            const unsigned long long az = pk2(a.z, a.z);
            const unsigned long long aw = pk2(a.w, a.w);
            pacc[0][0] = fma2(ax, xa.x, pacc[0][0]);
            pacc[0][1] = fma2(ax, xa.y, pacc[0][1]);
            pacc[0][2] = fma2(ax, xb.x, pacc[0][2]);
            pacc[0][3] = fma2(ax, xb.y, pacc[0][3]);
            pacc[1][0] = fma2(ay, xa.x, pacc[1][0]);
            pacc[1][1] = fma2(ay, xa.y, pacc[1][1]);
            pacc[1][2] = fma2(ay, xb.x, pacc[1][2]);
            pacc[1][3] = fma2(ay, xb.y, pacc[1][3]);
            pacc[2][0] = fma2(az, xa.x, pacc[2][0]);
            pacc[2][1] = fma2(az, xa.y, pacc[2][1]);
            pacc[2][2] = fma2(az, xb.x, pacc[2][2]);
            pacc[2][3] = fma2(az, xb.y, pacc[2][3]);
            pacc[3][0] = fma2(aw, xa.x, pacc[3][0]);
            pacc[3][1] = fma2(aw, xa.y, pacc[3][1]);
            pacc[3][2] = fma2(aw, xb.x, pacc[3][2]);
            pacc[3][3] = fma2(aw, xb.y, pacc[3][3]);
        }

#pragma unroll
        for (int mm = 0; mm < 4; ++mm) {
            float* dst = H2s + (m0 + mm) * HSTR + i0;
            const float2 p0 = up2(pacc[mm][0]);
            const float2 p1 = up2(pacc[mm][1]);
            const float2 p2 = up2(pacc[mm][2]);
            const float2 p3 = up2(pacc[mm][3]);
            float4 s0, s1;
            s0.x = fmaxf(p0.x, 0.f); s0.y = fmaxf(p0.y, 0.f);
            s0.z = fmaxf(p1.x, 0.f); s0.w = fmaxf(p1.y, 0.f);
            s1.x = fmaxf(p2.x, 0.f); s1.y = fmaxf(p2.y, 0.f);
            s1.z = fmaxf(p3.x, 0.f); s1.w = fmaxf(p3.y, 0.f);
            *reinterpret_cast<float4*>(dst)     = s0;
            *reinterpret_cast<float4*>(dst + 4) = s1;
        }
    }
    __syncthreads();

    // ---- stage C: layer3 GEMM (K=128), 4o x 4i tiles, f32x2 + layer4 ------
    {
        const int o0 = (tid >> 4) * 4;       // 0..60
        const int i0 = (tid & 15) * 4;       // 0..60

        unsigned long long pacc[4][2];       // [oo][item-pair]
#pragma unroll
        for (int mm = 0; mm < 4; ++mm) {
            const float b = b3[o0 + mm];
            const unsigned long long pb = pk2(b, b);
            pacc[mm][0] = pb; pacc[mm][1] = pb;
        }

#pragma unroll 4
        for (int k = 0; k < 128; ++k) {
            const float4 a = *reinterpret_cast<const float4*>(g_W3t + k * 64 + o0);
            const ulonglong2 xv =
                *reinterpret_cast<const ulonglong2*>(H2s + k * HSTR + i0);
            const unsigned long long ax = pk2(a.x, a.x);
            const unsigned long long ay = pk2(a.y, a.y);
            const unsigned long long az = pk2(a.z, a.z);
            const unsigned long long aw = pk2(a.w, a.w);
            pacc[0][0] = fma2(ax, xv.x, pacc[0][0]);
            pacc[0][1] = fma2(ax, xv.y, pacc[0][1]);
            pacc[1][0] = fma2(ay, xv.x, pacc[1][0]);
            pacc[1][1] = fma2(ay, xv.y, pacc[1][1]);
            pacc[2][0] = fma2(az, xv.x, pacc[2][0]);
            pacc[2][1] = fma2(az, xv.y, pacc[2][1]);
            pacc[3][0] = fma2(aw, xv.x, pacc[3][0]);
            pacc[3][1] = fma2(aw, xv.y, pacc[3][1]);
        }

        // unpack, relu, partial layer4 dot over this thread's 4 o's
        const float4 w4 = *reinterpret_cast<const float4*>(W4 + o0);
        const int to = tid >> 4;
        float h[4][4];
#pragma unroll
        for (int mm = 0; mm < 4; ++mm) {
            const float2 q0 = up2(pacc[mm][0]);
            const float2 q1 = up2(pacc[mm][1]);
            h[mm][0] = fmaxf(q0.x, 0.f); h[mm][1] = fmaxf(q0.y, 0.f);
            h[mm][2] = fmaxf(q1.x, 0.f); h[mm][3] = fmaxf(q1.y, 0.f);
        }
#pragma unroll
        for (int ii = 0; ii < 4; ++ii) {
            float p;
            p = __fmul_rn(w4.x, h[0][ii]);
            p = fmaf(w4.y, h[1][ii], p);
            p = fmaf(w4.z, h[2][ii], p);
            p = fmaf(w4.w, h[3][ii], p);
            red[to * HSTR + i0 + ii] = p;
        }
    }
    __syncthreads();

    // final: one thread per item sums 16 partials
    if (tid < TILE_I) {
        const int item = blockIdx.x * TILE_I + tid;
        float s = red[tid];
#pragma unroll
        for (int g = 1; g < 16; ++g) s += red[g * HSTR + tid];
        out[item] = (s + b4[0]) * masks[tid];
    }
}

extern "C" void kernel_launch(void* const* d_in, const int* in_sizes, int n_in,
                              void* d_out, int out_size) {
    const float* x  = (const float*)d_in[0];
    const float* r  = (const float*)d_in[1];
    const float* W1 = (const float*)d_in[2];
    const float* b1 = (const float*)d_in[3];
    const float* W2 = (const float*)d_in[4];
    const float* b2 = (const float*)d_in[5];
    const float* W3 = (const float*)d_in[6];
    const float* b3 = (const float*)d_in[7];
    const float* W4 = (const float*)d_in[8];
    const float* b4 = (const float*)d_in[9];
    float* out = (float*)d_out;

    cudaFuncSetAttribute(fused_mlp_kernel,
                         cudaFuncAttributeMaxDynamicSharedMemorySize, SMEM_BYTES);

    topk_filter_kernel<<<NAG, T1>>>(x);
    topk_extract_kernel<<<NAG / 8, 256>>>(x);
    transpose_kernel<<<32, 256>>>(W2, W3);
    fused_mlp_kernel<<<NITEMS / TILE_I, 256, SMEM_BYTES>>>(
        x, r, W1, b1, b2, b3, W4, b4, out);
}